// round 4
// baseline (speedup 1.0000x reference)
#include <cuda_runtime.h>
#include <cuda_bf16.h>

// SAN Subtraction: out[n,c,k,l] = x[n,c,oh,ow] - x[n,c, refl(oh+i-3), refl(ow+j-3)]
//   x: [8, 64, 56, 56] fp32, K=7, stride=1, pad=3 (reflect)
//   out: [8, 64, 49, 3136] fp32
//
// R3 strategy:
//  - 2 CTAs per (n,c) plane (half-plane each, 28 output rows) -> grid=1024,
//    block=128, ~7 CTAs/SM: better balance (8% tail vs 15%) + higher occupancy.
//  - Pre-reflected PADDED smem tile (34 rows x 62 cols, row stride 88 floats).
//    Hot loop has no reflect math; each kernel row read as 3 aligned LDS.128.
//    Row stride 88 (== 24 mod 32) makes every 8-lane LDS.128 phase bank-
//    conflict-free (verified per-phase bank map).
//  - Center extracted from the i==3 row registers (no separate loads).
//  - __stcs streaming stores: the 315 MB write stream bypasses L2 retention.

#define H 56
#define W 56
#define PLANE (H * W)   // 3136
#define KK 49
#define RPC 28          // output rows per CTA
#define SROWS 34        // staged rows: RPC + 2*3 halo
#define PCOLS 62        // padded cols used: W + 6
#define RS 88           // smem row stride in floats (24 mod 32 -> conflict-free)

__global__ __launch_bounds__(128, 8)
void san_subtraction_kernel(const float* __restrict__ x,
                            float* __restrict__ out) {
    __shared__ float sp[SROWS * RS];

    const int plane = blockIdx.x >> 1;
    const int half  = blockIdx.x & 1;
    const int r0    = half * RPC;

    const float* __restrict__ xin = x + (size_t)plane * PLANE;

    // Stage pre-reflected padded tile: rows r0-3 .. r0+30, cols -3 .. 58.
    // refl(p) = min(|p|, 110-|p|)  (110 = 2*(H-1))
    for (int t = threadIdx.x; t < SROWS * PCOLS; t += 128) {
        const int lr = t / PCOLS;
        const int pc = t - lr * PCOLS;
        int g = r0 + lr - 3;
        g = g < 0 ? -g : g;
        g = g < 110 - g ? g : 110 - g;
        int w = pc - 3;
        w = w < 0 ? -w : w;
        w = w < 110 - w ? w : 110 - w;
        sp[lr * RS + pc] = xin[g * W + w];
    }
    __syncthreads();

    float* __restrict__ ob0 =
        out + (size_t)plane * KK * PLANE + (size_t)r0 * W;

    const int NP = RPC * (W / 4);  // 392 float4 positions in this half
    for (int pos = threadIdx.x; pos < NP; pos += 128) {
        const int lrow = pos / 14;         // 0..27 output row within half
        const int w0   = (pos - lrow * 14) * 4;

        // Center from padded row (lrow+3): pc = w0+3..w0+6 lives in the
        // 3 aligned float4s at [w0, w0+12).
        float4 center;
        {
            const float4* p =
                reinterpret_cast<const float4*>(sp + (lrow + 3) * RS + w0);
            float4 A = p[0], B = p[1];
            center = make_float4(A.w, B.x, B.y, B.z);
        }

        float* __restrict__ ob = ob0 + lrow * W + w0;

#pragma unroll
        for (int i = 0; i < 7; ++i) {
            const float4* p =
                reinterpret_cast<const float4*>(sp + (lrow + i) * RS + w0);
            const float4 A = p[0], B = p[1], C = p[2];
            const float v[12] = {A.x, A.y, A.z, A.w,
                                 B.x, B.y, B.z, B.w,
                                 C.x, C.y, C.z, C.w};
#pragma unroll
            for (int j = 0; j < 7; ++j) {
                float4 r;
                r.x = center.x - v[j];
                r.y = center.y - v[j + 1];
                r.z = center.z - v[j + 2];
                r.w = center.w - v[j + 3];
                // lanes are consecutive pos at fixed (i,j): each warp store
                // group is 512 contiguous bytes. Streaming hint: evict-first.
                __stcs(reinterpret_cast<float4*>(ob + (i * 7 + j) * PLANE), r);
            }
        }
    }
}

extern "C" void kernel_launch(void* const* d_in, const int* in_sizes, int n_in,
                              void* d_out, int out_size) {
    const float* x = (const float*)d_in[0];
    float* out = (float*)d_out;
    const int planes = in_sizes[0] / PLANE;  // 512
    san_subtraction_kernel<<<planes * 2, 128>>>(x, out);
}

// round 5
// speedup vs baseline: 1.1389x; 1.1389x over previous
#include <cuda_runtime.h>
#include <cuda_bf16.h>

// SAN Subtraction: out[n,c,k,l] = x[n,c,oh,ow] - x[n,c, refl(oh+i-3), refl(ow+j-3)]
//   x: [8, 64, 56, 56] fp32, K=7, stride=1, pad=3 (reflect)
//   out: [8, 64, 49, 3136] fp32  (315 MB write stream = the roofline)
//
// R4: R2 launch shape (1 CTA/plane, 256 thr) + R3 padded-tile idea, fixed:
//  - __launch_bounds__(256,3): 85-reg budget -> no local-memory spills
//    (R3 pinned at the 64-reg cap and spilled; L1 68%, DRAM 43%).
//  - Pre-reflected padded tile 62 rows x 62 cols, row stride 88 floats.
//    Hot loop: 21 LDS.128 + 49 STG.128 per float4 position, zero reflect math.
//    Stride 88 (22 groups of 16B, 22 mod 8 = 6): every 8-lane LDS.128 phase
//    hits 8 distinct 16B bank groups, incl. row-straddling phases -> no
//    conflicts. MIO cost drops from ~36us (R2 4-way-conflict scalar LDS)
//    to ~2us, below the DRAM-write floor.
//  - Plain stores (no __stcs).

#define H 56
#define W 56
#define PLANE (H * W)        // 3136
#define KK 49
#define PROWS 62             // H + 2*3 halo
#define PCOLS 62             // W + 2*3 halo
#define RS 88                // smem row stride in floats (16B-group coprime)
#define NPOS (H * (W / 4))   // 784 float4 positions per plane

__global__ __launch_bounds__(256, 3)
void san_subtraction_kernel(const float* __restrict__ x,
                            float* __restrict__ out) {
    __shared__ float sp[PROWS * RS];

    const int plane = blockIdx.x;
    const float* __restrict__ xin = x + (size_t)plane * PLANE;

    // Stage pre-reflected padded tile: padded (lr,pc) -> input (lr-3, pc-3)
    // reflected.  refl(p) = min(|p|, 110-|p|), 110 = 2*(H-1).
    for (int t = threadIdx.x; t < PROWS * PCOLS; t += 256) {
        const int lr = t / PCOLS;
        const int pc = t - lr * PCOLS;
        int g = lr - 3;
        g = g < 0 ? -g : g;
        g = g < 110 - g ? g : 110 - g;
        int w = pc - 3;
        w = w < 0 ? -w : w;
        w = w < 110 - w ? w : 110 - w;
        sp[lr * RS + pc] = xin[g * W + w];
    }
    __syncthreads();

    float* __restrict__ obase = out + (size_t)plane * KK * PLANE;

    for (int pos = threadIdx.x; pos < NPOS; pos += 256) {
        const int lrow = pos / 14;              // output row 0..55
        const int w0   = (pos - lrow * 14) * 4; // output col base

        // Center cols w0..w0+3 live at padded cols w0+3..w0+6 of row lrow+3,
        // i.e. inside the two aligned float4s at [w0, w0+8).
        float4 center;
        {
            const float4* p =
                reinterpret_cast<const float4*>(sp + (lrow + 3) * RS + w0);
            const float4 A = p[0], B = p[1];
            center = make_float4(A.w, B.x, B.y, B.z);
        }

        float* __restrict__ ob = obase + lrow * W + w0;

#pragma unroll
        for (int i = 0; i < 7; ++i) {
            const float4* p =
                reinterpret_cast<const float4*>(sp + (lrow + i) * RS + w0);
            const float4 A = p[0], B = p[1], C = p[2];
            // Padded cols w0 .. w0+11 == input cols w0-3 .. w0+8.
            const float v0 = A.x, v1 = A.y, v2 = A.z, v3 = A.w;
            const float v4 = B.x, v5 = B.y, v6 = B.z, v7 = B.w;
            const float v8 = C.x, v9 = C.y, v10 = C.z, v11 = C.w;
            const float vv[12] = {v0, v1, v2, v3, v4, v5,
                                  v6, v7, v8, v9, v10, v11};
#pragma unroll
            for (int j = 0; j < 7; ++j) {
                float4 r;
                r.x = center.x - vv[j];
                r.y = center.y - vv[j + 1];
                r.z = center.z - vv[j + 2];
                r.w = center.w - vv[j + 3];
                // Lanes hold consecutive pos at fixed (i,j): each warp's
                // STG.128 group writes 512 contiguous bytes.
                *reinterpret_cast<float4*>(ob + (i * 7 + j) * PLANE) = r;
            }
        }
    }
}

extern "C" void kernel_launch(void* const* d_in, const int* in_sizes, int n_in,
                              void* d_out, int out_size) {
    const float* x = (const float*)d_in[0];
    float* out = (float*)d_out;
    const int planes = in_sizes[0] / PLANE;  // 512
    san_subtraction_kernel<<<planes, 256>>>(x, out);
}

// round 6
// speedup vs baseline: 1.2038x; 1.0571x over previous
#include <cuda_runtime.h>
#include <cuda_bf16.h>

// SAN Subtraction: out[n,c,k,l] = x[n,c,oh,ow] - x[n,c, refl(oh+i-3), refl(ow+j-3)]
//   x: [8, 64, 56, 56] fp32, K=7, stride=1, pad=3 (reflect)
//   out: [8, 64, 49, 3136] fp32 (315 MB write stream)
//
// R5: R3's launch shape + R4's proven 58-reg hot loop.
//  - 128 thr/CTA, half-plane (28 rows) per CTA, grid=1024,
//    __launch_bounds__(128,8): 32 warps/SM (50% occ) AND the whole grid is
//    resident in ONE wave (148*8=1184 >= 1024) -> no tail imbalance.
//  - Plain STG.128 (R3's __stcs was what blew the 64-reg cap and spilled;
//    R4 compiled the identical loop to 58 regs with plain stores).
//  - Pre-reflected padded tile 34x62, row stride 88 floats: LDS.128
//    conflict-free (22 16B-groups/row, 22 mod 8 = 6 -> all 8-lane phases
//    hit 8 distinct bank groups).

#define H 56
#define W 56
#define PLANE (H * W)   // 3136
#define KK 49
#define RPC 28          // output rows per CTA
#define SROWS 34        // RPC + 2*3 halo
#define PCOLS 62        // W + 6
#define RS 88           // smem row stride in floats

__global__ __launch_bounds__(128, 8)
void san_subtraction_kernel(const float* __restrict__ x,
                            float* __restrict__ out) {
    __shared__ float sp[SROWS * RS];

    const int plane = blockIdx.x >> 1;
    const int half  = blockIdx.x & 1;
    const int r0    = half * RPC;

    const float* __restrict__ xin = x + (size_t)plane * PLANE;

    // Stage pre-reflected padded tile: rows r0-3 .. r0+30, cols -3 .. 58.
    // refl(p) = min(|p|, 110-|p|)  (110 = 2*(H-1))
    for (int t = threadIdx.x; t < SROWS * PCOLS; t += 128) {
        const int lr = t / PCOLS;
        const int pc = t - lr * PCOLS;
        int g = r0 + lr - 3;
        g = g < 0 ? -g : g;
        g = g < 110 - g ? g : 110 - g;
        int w = pc - 3;
        w = w < 0 ? -w : w;
        w = w < 110 - w ? w : 110 - w;
        sp[lr * RS + pc] = xin[g * W + w];
    }
    __syncthreads();

    float* __restrict__ ob0 =
        out + (size_t)plane * KK * PLANE + (size_t)r0 * W;

    const int NP = RPC * (W / 4);  // 392 float4 positions in this half
    for (int pos = threadIdx.x; pos < NP; pos += 128) {
        const int lrow = pos / 14;              // 0..27
        const int w0   = (pos - lrow * 14) * 4;

        // Center cols w0..w0+3 = padded cols w0+3..w0+6 of row lrow+3:
        // inside the two aligned float4s at [w0, w0+8).
        float4 center;
        {
            const float4* p =
                reinterpret_cast<const float4*>(sp + (lrow + 3) * RS + w0);
            const float4 A = p[0], B = p[1];
            center = make_float4(A.w, B.x, B.y, B.z);
        }

        float* __restrict__ ob = ob0 + lrow * W + w0;

#pragma unroll
        for (int i = 0; i < 7; ++i) {
            const float4* p =
                reinterpret_cast<const float4*>(sp + (lrow + i) * RS + w0);
            const float4 A = p[0], B = p[1], C = p[2];
            const float vv[12] = {A.x, A.y, A.z, A.w,
                                  B.x, B.y, B.z, B.w,
                                  C.x, C.y, C.z, C.w};
#pragma unroll
            for (int j = 0; j < 7; ++j) {
                float4 r;
                r.x = center.x - vv[j];
                r.y = center.y - vv[j + 1];
                r.z = center.z - vv[j + 2];
                r.w = center.w - vv[j + 3];
                // Lanes hold consecutive pos at fixed (i,j): each warp's
                // STG.128 group writes 512 contiguous bytes.
                *reinterpret_cast<float4*>(ob + (i * 7 + j) * PLANE) = r;
            }
        }
    }
}

extern "C" void kernel_launch(void* const* d_in, const int* in_sizes, int n_in,
                              void* d_out, int out_size) {
    const float* x = (const float*)d_in[0];
    float* out = (float*)d_out;
    const int planes = in_sizes[0] / PLANE;  // 512
    san_subtraction_kernel<<<planes * 2, 128>>>(x, out);
}